// round 6
// baseline (speedup 1.0000x reference)
#include <cuda_runtime.h>
#include <cstdint>

// FastSeqProp: instance-norm(L=200) -> scale/shift -> softmax over C=4
// -> exact JAX threefry categorical (key 42, partitionable) -> straight-through
// -> pad to (N,4,600); outputs [softmax_padded, sampled_padded].
//
// R6: register diet + phase reorder. Threefry runs first with minimal live
// state; ts/weights load after. __launch_bounds__(256,8) -> 32 regs, 64
// warps/SM. All float math bit-identical to the validated R5 kernel
// (rel_err 5.77e-4 = one tolerated argmax flip).

#define LEN   200
#define LPAD  600
#define NCH   4
#define EPSV  1e-5f
#define TINYF 1.17549435e-38f

__device__ __forceinline__ uint32_t rotl32(uint32_t x, int r) {
    return (x << r) | (x >> (32 - r));
}

__device__ __forceinline__ void tf_round(uint32_t& x0, uint32_t& x1, int r) {
    x0 += x1;
    x1 = rotl32(x1, r);
    x1 ^= x0;
}

__device__ __forceinline__ uint32_t tf_bits_k42(uint32_t idx) {
    // threefry2x32, key=(0,42), counter=(0, idx); out = x0 ^ x1 (partitionable)
    const uint32_t ks0 = 0u;
    const uint32_t ks1 = 42u;
    const uint32_t ks2 = 0x1BD11BDAu ^ ks0 ^ ks1;
    uint32_t x0 = 0u + ks0;
    uint32_t x1 = idx + ks1;

    tf_round(x0, x1, 13); tf_round(x0, x1, 15); tf_round(x0, x1, 26); tf_round(x0, x1, 6);
    x0 += ks1; x1 += ks2 + 1u;
    tf_round(x0, x1, 17); tf_round(x0, x1, 29); tf_round(x0, x1, 16); tf_round(x0, x1, 24);
    x0 += ks2; x1 += ks0 + 2u;
    tf_round(x0, x1, 13); tf_round(x0, x1, 15); tf_round(x0, x1, 26); tf_round(x0, x1, 6);
    x0 += ks0; x1 += ks1 + 3u;
    tf_round(x0, x1, 17); tf_round(x0, x1, 29); tf_round(x0, x1, 16); tf_round(x0, x1, 24);
    x0 += ks1; x1 += ks2 + 4u;
    tf_round(x0, x1, 13); tf_round(x0, x1, 15); tf_round(x0, x1, 26); tf_round(x0, x1, 6);
    x0 += ks2; x1 += ks0 + 5u;

    return x0 ^ x1;
}

// w = -log(u), u = uniform in [tiny,1) from bits; exact logf (matches XLA).
__device__ __forceinline__ float expw_from_bits(uint32_t bits) {
    float f = __uint_as_float((bits >> 9) | 0x3f800000u) - 1.0f;
    float u = fmaxf(f, TINYF);
    return 0.0f - logf(u);
}

__global__ __launch_bounds__(256, 8) void fastseqprop_kernel(
    const float* __restrict__ ts,    // (N,4,200)
    const float* __restrict__ scw,   // (N,4,1)
    const float* __restrict__ shw,   // (N,4,1)
    const float* __restrict__ up,    // (N,4,200)
    const float* __restrict__ dn,    // (N,4,200)
    float* __restrict__ out,         // (2,N,4,600) flattened
    uint32_t half_out)               // N*4*600
{
    const uint32_t n    = blockIdx.x;
    const uint32_t t    = threadIdx.x;
    const uint32_t lane = t & 31u;
    const uint32_t wid  = t >> 5;
    const bool act = (t < LEN);

    __shared__ float red[8][4];
    __shared__ float bcm[4];            // means
    __shared__ float bcr[4];            // rsqrt(var+eps)
    __shared__ float sw[NCH * LEN];     // w = -log(u), layout [c*200 + l]

    const uint32_t base = n * (NCH * LEN);   // == flat gumbel base (N,L,4)

    // ---- phase 1: dense threefry, minimal live registers ----
    // 800 draws; 3 per thread, 4th on warp 7 (idle in element phase).
    {
        const uint32_t j0 = t;
        const uint32_t j1 = t + 256u;
        const uint32_t j2 = t + 512u;
        const uint32_t b0 = tf_bits_k42(base + j0);
        const uint32_t b1 = tf_bits_k42(base + j1);
        const uint32_t b2 = tf_bits_k42(base + j2);
        sw[(j0 & 3u) * LEN + (j0 >> 2)] = expw_from_bits(b0);
        sw[(j1 & 3u) * LEN + (j1 >> 2)] = expw_from_bits(b1);
        sw[(j2 & 3u) * LEN + (j2 >> 2)] = expw_from_bits(b2);
        if (t >= 224u) {
            const uint32_t j3 = (t - 224u) + 768u;
            const uint32_t b3 = tf_bits_k42(base + j3);
            sw[(j3 & 3u) * LEN + (j3 >> 2)] = expw_from_bits(b3);
        }
    }

    // ---- phase 2: load ts (latency covered by other CTAs' threefry) ----
    float x0 = 0.f, x1 = 0.f, x2 = 0.f, x3 = 0.f;
    if (act) {
        x0 = ts[base + 0 * LEN + t];
        x1 = ts[base + 1 * LEN + t];
        x2 = ts[base + 2 * LEN + t];
        x3 = ts[base + 3 * LEN + t];
    }

    // ---- pass 1: sums -> means (bit-identical tree; /200 hoisted to t0) ----
    {
        float v0 = x0, v1 = x1, v2 = x2, v3 = x3;
        #pragma unroll
        for (int o = 16; o > 0; o >>= 1) {
            v0 += __shfl_down_sync(0xffffffffu, v0, o);
            v1 += __shfl_down_sync(0xffffffffu, v1, o);
            v2 += __shfl_down_sync(0xffffffffu, v2, o);
            v3 += __shfl_down_sync(0xffffffffu, v3, o);
        }
        if (lane == 0) { red[wid][0] = v0; red[wid][1] = v1; red[wid][2] = v2; red[wid][3] = v3; }
        __syncthreads();
        if (t == 0) {
            float s0 = 0.f, s1 = 0.f, s2 = 0.f, s3 = 0.f;
            #pragma unroll
            for (int w = 0; w < 8; w++) { s0 += red[w][0]; s1 += red[w][1]; s2 += red[w][2]; s3 += red[w][3]; }
            bcm[0] = s0 / 200.0f; bcm[1] = s1 / 200.0f;
            bcm[2] = s2 / 200.0f; bcm[3] = s3 / 200.0f;
        }
        __syncthreads();
    }
    const float d0 = act ? (x0 - bcm[0]) : 0.f;
    const float d1 = act ? (x1 - bcm[1]) : 0.f;
    const float d2 = act ? (x2 - bcm[2]) : 0.f;
    const float d3 = act ? (x3 - bcm[3]) : 0.f;

    // ---- pass 2: centered sum of squares -> rsqrt(var+eps) (hoisted) ----
    {
        float v0 = d0 * d0, v1 = d1 * d1, v2 = d2 * d2, v3 = d3 * d3;
        #pragma unroll
        for (int o = 16; o > 0; o >>= 1) {
            v0 += __shfl_down_sync(0xffffffffu, v0, o);
            v1 += __shfl_down_sync(0xffffffffu, v1, o);
            v2 += __shfl_down_sync(0xffffffffu, v2, o);
            v3 += __shfl_down_sync(0xffffffffu, v3, o);
        }
        if (lane == 0) { red[wid][0] = v0; red[wid][1] = v1; red[wid][2] = v2; red[wid][3] = v3; }
        __syncthreads();
        if (t == 0) {
            float s0 = 0.f, s1 = 0.f, s2 = 0.f, s3 = 0.f;
            #pragma unroll
            for (int w = 0; w < 8; w++) { s0 += red[w][0]; s1 += red[w][1]; s2 += red[w][2]; s3 += red[w][3]; }
            bcr[0] = rsqrtf(s0 / 200.0f + EPSV);
            bcr[1] = rsqrtf(s1 / 200.0f + EPSV);
            bcr[2] = rsqrtf(s2 / 200.0f + EPSV);
            bcr[3] = rsqrtf(s3 / 200.0f + EPSV);
        }
        __syncthreads();
    }

    if (!act) return;

    // weights loaded here (not held across threefry)
    const uint32_t wbase = n * NCH;
    float sc[4];
    sc[0] = (d0 * bcr[0]) * scw[wbase + 0] + shw[wbase + 0];
    sc[1] = (d1 * bcr[1]) * scw[wbase + 1] + shw[wbase + 1];
    sc[2] = (d2 * bcr[2]) * scw[wbase + 2] + shw[wbase + 2];
    sc[3] = (d3 * bcr[3]) * scw[wbase + 3] + shw[wbase + 3];

    // softmax over channels; exact expf (feeds argmin), fast divide for probs
    const float mx  = fmaxf(fmaxf(sc[0], sc[1]), fmaxf(sc[2], sc[3]));
    float ex[4];
    #pragma unroll
    for (int c = 0; c < 4; c++) ex[c] = expf(sc[c] - mx);
    const float ssum = ((ex[0] + ex[1]) + ex[2]) + ex[3];
    float soft[4];
    #pragma unroll
    for (int c = 0; c < 4; c++) soft[c] = __fdividef(ex[c], ssum);

    // ---- exponential-races argmin: argmin_c w_c / ex_c (cross-multiplied) ----
    float wb = sw[t];
    float eb = ex[0];
    int   bi = 0;
    #pragma unroll
    for (int c = 1; c < 4; c++) {
        const float wc = sw[(uint32_t)c * LEN + t];
        if (wc * eb < wb * ex[c]) { wb = wc; eb = ex[c]; bi = c; }
    }

    // ---- write outputs (direct scalar stores) ----
    float* out0 = out;
    float* out1 = out + half_out;
    const uint32_t obase = n * (NCH * LPAD);

    #pragma unroll
    for (int c = 0; c < 4; c++) {
        const float u_v = up[base + (uint32_t)c * LEN + t];
        const float d_v = dn[base + (uint32_t)c * LEN + t];
        const float s_v = soft[c];
        const float oh  = (c == bi) ? 1.0f : 0.0f;
        const float samp = (oh - s_v) + s_v;   // straight-through

        const uint32_t row = obase + (uint32_t)c * LPAD;
        out0[row + t]           = u_v;
        out0[row + LEN + t]     = s_v;
        out0[row + 2 * LEN + t] = d_v;
        out1[row + t]           = u_v;
        out1[row + LEN + t]     = samp;
        out1[row + 2 * LEN + t] = d_v;
    }
}

extern "C" void kernel_launch(void* const* d_in, const int* in_sizes, int n_in,
                              void* d_out, int out_size) {
    const float* ts  = (const float*)d_in[0];
    const float* scw = (const float*)d_in[1];
    const float* shw = (const float*)d_in[2];
    const float* up  = (const float*)d_in[3];
    const float* dn  = (const float*)d_in[4];
    float* out = (float*)d_out;

    const int nseq = in_sizes[0] / (NCH * LEN);          // 8192
    const uint32_t half_out = (uint32_t)(out_size / 2);  // N*4*600

    fastseqprop_kernel<<<nseq, 256>>>(ts, scw, shw, up, dn, out, half_out);
}